// round 2
// baseline (speedup 1.0000x reference)
#include <cuda_runtime.h>
#include <math_constants.h>

// Problem constants
#define BATCH   64
#define SEQL    256
#define EDIM    512
#define SDIM    1024
#define KDIM    1024   // 2*E
#define NCLASS  2

// GEMM tile config
#define BM 128
#define BN 128
#define BKK 16
#define TM 8
#define TN 8

// Scratch (static device globals; no allocations allowed)
__device__ float g_embs[BATCH * SEQL * EDIM];     // 33.5 MB gathered embeddings
__device__ float g_sentpre[BATCH * SDIM];         // pre-sigmoid max-pool accumulator

__device__ __forceinline__ void atomicMaxFloat(float* addr, float val) {
    // standard bit-trick: positive floats order like ints, negative like reversed unsigned
    if (val >= 0.0f) {
        atomicMax(reinterpret_cast<int*>(addr), __float_as_int(val));
    } else {
        atomicMin(reinterpret_cast<unsigned int*>(addr), __float_as_uint(val));
    }
}

// ---------------------------------------------------------------------------
// Kernel 1: embedding gather.  One block per (b,l) row, 128 threads x float4.
// ---------------------------------------------------------------------------
__global__ void gather_kernel(const int* __restrict__ inputs,
                              const float* __restrict__ emb_table) {
    int row = blockIdx.x;                 // 0 .. BATCH*SEQL-1
    int tok = inputs[row];
    const float4* src = reinterpret_cast<const float4*>(emb_table + (size_t)tok * EDIM);
    float4* dst = reinterpret_cast<float4*>(g_embs + (size_t)row * EDIM);
    dst[threadIdx.x] = src[threadIdx.x];  // 128 threads * 4 floats = 512 = EDIM
}

// ---------------------------------------------------------------------------
// Kernel 2: init max accumulator to -inf
// ---------------------------------------------------------------------------
__global__ void init_kernel() {
    int i = blockIdx.x * blockDim.x + threadIdx.x;
    if (i < BATCH * SDIM) g_sentpre[i] = -CUDART_INF_F;
}

// ---------------------------------------------------------------------------
// Kernel 3: fused conv GEMM + max-pool.
//   conv[b,l,s] = dot(g_embs[b, l*512 : l*512+1024], Wc[s,:]) + bc[s]
//   (pairs row l is contiguous in g_embs with row stride 512)
//   g_sentpre[b,s] = max_l conv[b,l,s]   (via block reduce + atomicMaxFloat)
// Grid: (SDIM/BN, ceil(255/BM), BATCH), 256 threads.
// ---------------------------------------------------------------------------
__global__ __launch_bounds__(256) void conv_max_kernel(
    const float* __restrict__ Wc, const float* __restrict__ bc)
{
    const int b  = blockIdx.z;
    const int m0 = blockIdx.y * BM;     // l-tile offset
    const int n0 = blockIdx.x * BN;     // s-tile offset
    const float* A = g_embs + (size_t)b * SEQL * EDIM;

    __shared__ float As[BKK][BM];
    __shared__ float Bs[BKK][BN];
    __shared__ float red[16][BN];

    const int tid  = threadIdx.x;
    const int trow = tid >> 4;          // 0..15
    const int tcol = tid & 15;          // 0..15
    const int tm   = trow * TM;
    const int tn   = tcol * TN;

    float acc[TM][TN];
#pragma unroll
    for (int i = 0; i < TM; i++)
#pragma unroll
        for (int j = 0; j < TN; j++) acc[i][j] = 0.0f;

    for (int k0 = 0; k0 < KDIM; k0 += BKK) {
        // --- load A tile: 128 rows x 16 cols = 512 float4, 2 per thread ---
#pragma unroll
        for (int q = 0; q < 2; q++) {
            int lid = tid + 256 * q;
            int ar  = lid >> 2;               // 0..127
            int ac  = (lid & 3) << 2;         // 0,4,8,12
            int gl  = m0 + ar;                // global l
            float4 v = make_float4(0.f, 0.f, 0.f, 0.f);
            if (gl < SEQL - 1)
                v = *reinterpret_cast<const float4*>(A + (size_t)gl * EDIM + k0 + ac);
            As[ac + 0][ar] = v.x; As[ac + 1][ar] = v.y;
            As[ac + 2][ar] = v.z; As[ac + 3][ar] = v.w;
        }
        // --- load B tile: Wc[s,k], 128 rows x 16 cols ---
#pragma unroll
        for (int q = 0; q < 2; q++) {
            int lid = tid + 256 * q;
            int br  = lid >> 2;
            int bcc = (lid & 3) << 2;
            float4 v = *reinterpret_cast<const float4*>(
                Wc + (size_t)(n0 + br) * KDIM + k0 + bcc);
            Bs[bcc + 0][br] = v.x; Bs[bcc + 1][br] = v.y;
            Bs[bcc + 2][br] = v.z; Bs[bcc + 3][br] = v.w;
        }
        __syncthreads();

#pragma unroll
        for (int k = 0; k < BKK; k++) {
            float ra[TM], rb[TN];
            // vector reads from smem (8 consecutive floats each)
            *reinterpret_cast<float4*>(&ra[0]) = *reinterpret_cast<const float4*>(&As[k][tm]);
            *reinterpret_cast<float4*>(&ra[4]) = *reinterpret_cast<const float4*>(&As[k][tm + 4]);
            *reinterpret_cast<float4*>(&rb[0]) = *reinterpret_cast<const float4*>(&Bs[k][tn]);
            *reinterpret_cast<float4*>(&rb[4]) = *reinterpret_cast<const float4*>(&Bs[k][tn + 4]);
#pragma unroll
            for (int i = 0; i < TM; i++)
#pragma unroll
                for (int j = 0; j < TN; j++)
                    acc[i][j] = fmaf(ra[i], rb[j], acc[i][j]);
        }
        __syncthreads();
    }

    // --- epilogue: add bias, per-thread max over valid rows ---
    float bcv[TN];
#pragma unroll
    for (int j = 0; j < TN; j++) bcv[j] = __ldg(&bc[n0 + tn + j]);

    float cmax[TN];
#pragma unroll
    for (int j = 0; j < TN; j++) cmax[j] = -CUDART_INF_F;

#pragma unroll
    for (int i = 0; i < TM; i++) {
        int gl = m0 + tm + i;
        if (gl < SEQL - 1) {
#pragma unroll
            for (int j = 0; j < TN; j++)
                cmax[j] = fmaxf(cmax[j], acc[i][j] + bcv[j]);
        }
    }

    // --- tree reduce across the 16 row-groups ---
#pragma unroll
    for (int j = 0; j < TN; j++) red[trow][tn + j] = cmax[j];
    __syncthreads();
#pragma unroll
    for (int st = 8; st > 0; st >>= 1) {
        if (trow < st) {
#pragma unroll
            for (int j = 0; j < TN; j++)
                red[trow][tn + j] = fmaxf(red[trow][tn + j], red[trow + st][tn + j]);
        }
        __syncthreads();
    }
    if (trow == 0) {
#pragma unroll
        for (int j = 0; j < TN; j++)
            atomicMaxFloat(&g_sentpre[(size_t)b * SDIM + n0 + tn + j], red[0][tn + j]);
    }
}

// ---------------------------------------------------------------------------
// Kernel 4: sigmoid + classifier (S->50->2) + log_softmax. One block per b.
// ---------------------------------------------------------------------------
__global__ __launch_bounds__(128) void classifier_kernel(
    const float* __restrict__ W1, const float* __restrict__ b1,
    const float* __restrict__ W2, const float* __restrict__ b2,
    float* __restrict__ out)
{
    const int b = blockIdx.x;
    __shared__ float sent[SDIM];
    __shared__ float h[64];

    for (int i = threadIdx.x; i < SDIM; i += blockDim.x) {
        float v = g_sentpre[(size_t)b * SDIM + i];
        sent[i] = 1.0f / (1.0f + expf(-v));
    }
    __syncthreads();

    const int w    = threadIdx.x >> 5;
    const int lane = threadIdx.x & 31;
    for (int j = w; j < 50; j += 4) {
        float sum = 0.0f;
        const float* wrow = W1 + (size_t)j * SDIM;
        for (int i = lane; i < SDIM; i += 32) sum = fmaf(sent[i], wrow[i], sum);
#pragma unroll
        for (int o = 16; o > 0; o >>= 1) sum += __shfl_down_sync(0xffffffffu, sum, o);
        if (lane == 0) h[j] = sum + b1[j];
    }
    __syncthreads();

    if (threadIdx.x == 0) {
        float l0 = b2[0], l1 = b2[1];
        for (int j = 0; j < 50; j++) {
            l0 = fmaf(h[j], W2[j], l0);
            l1 = fmaf(h[j], W2[50 + j], l1);
        }
        float m   = fmaxf(l0, l1);
        float lse = m + logf(expf(l0 - m) + expf(l1 - m));
        out[b * NCLASS + 0] = l0 - lse;
        out[b * NCLASS + 1] = l1 - lse;
    }
}

// ---------------------------------------------------------------------------
// kernel_launch
// inputs order: inputs(int32), emb_table, Wc, bc, W1, b1, W2, b2
// ---------------------------------------------------------------------------
extern "C" void kernel_launch(void* const* d_in, const int* in_sizes, int n_in,
                              void* d_out, int out_size) {
    const int*   inputs = (const int*)  d_in[0];
    const float* emb    = (const float*)d_in[1];
    const float* Wc     = (const float*)d_in[2];
    const float* bc     = (const float*)d_in[3];
    const float* W1     = (const float*)d_in[4];
    const float* b1     = (const float*)d_in[5];
    const float* W2     = (const float*)d_in[6];
    const float* b2     = (const float*)d_in[7];
    float* out = (float*)d_out;

    gather_kernel<<<BATCH * SEQL, 128>>>(inputs, emb);
    init_kernel<<<(BATCH * SDIM + 255) / 256, 256>>>();

    dim3 grid(SDIM / BN, (SEQL - 1 + BM - 1) / BM, BATCH);
    conv_max_kernel<<<grid, 256>>>(Wc, bc);

    classifier_kernel<<<BATCH, 128>>>(W1, b1, W2, b2, out);
}

// round 3
// speedup vs baseline: 1.0004x; 1.0004x over previous
#include <cuda_runtime.h>
#include <math_constants.h>

// Problem constants
#define BATCH   64
#define SEQL    256
#define EDIM    512
#define SDIM    1024
#define KDIM    1024   // 2*E
#define NCLASS  2

// GEMM tile config
#define BM 128
#define BN 128
#define BKK 16
#define TM 8
#define TN 8

// Scratch (static device globals; no allocations allowed)
__device__ float g_embs[BATCH * SEQL * EDIM];     // 33.5 MB gathered embeddings
__device__ float g_sentpre[BATCH * SDIM];         // pre-sigmoid max-pool accumulator

__device__ __forceinline__ void atomicMaxFloat(float* addr, float val) {
    // standard bit-trick: positive floats order like ints, negative like reversed unsigned
    if (val >= 0.0f) {
        atomicMax(reinterpret_cast<int*>(addr), __float_as_int(val));
    } else {
        atomicMin(reinterpret_cast<unsigned int*>(addr), __float_as_uint(val));
    }
}

// ---------------------------------------------------------------------------
// Kernel 1: embedding gather.  One block per (b,l) row, 128 threads x float4.
// ---------------------------------------------------------------------------
__global__ void gather_kernel(const int* __restrict__ inputs,
                              const float* __restrict__ emb_table) {
    int row = blockIdx.x;                 // 0 .. BATCH*SEQL-1
    int tok = inputs[row];
    const float4* src = reinterpret_cast<const float4*>(emb_table + (size_t)tok * EDIM);
    float4* dst = reinterpret_cast<float4*>(g_embs + (size_t)row * EDIM);
    dst[threadIdx.x] = src[threadIdx.x];  // 128 threads * 4 floats = 512 = EDIM
}

// ---------------------------------------------------------------------------
// Kernel 2: init max accumulator to -inf
// ---------------------------------------------------------------------------
__global__ void init_kernel() {
    int i = blockIdx.x * blockDim.x + threadIdx.x;
    if (i < BATCH * SDIM) g_sentpre[i] = -CUDART_INF_F;
}

// ---------------------------------------------------------------------------
// Kernel 3: fused conv GEMM + max-pool.
//   conv[b,l,s] = dot(g_embs[b, l*512 : l*512+1024], Wc[s,:]) + bc[s]
//   (pairs row l is contiguous in g_embs with row stride 512)
//   g_sentpre[b,s] = max_l conv[b,l,s]   (via block reduce + atomicMaxFloat)
// Grid: (SDIM/BN, ceil(255/BM), BATCH), 256 threads.
// ---------------------------------------------------------------------------
__global__ __launch_bounds__(256) void conv_max_kernel(
    const float* __restrict__ Wc, const float* __restrict__ bc)
{
    const int b  = blockIdx.z;
    const int m0 = blockIdx.y * BM;     // l-tile offset
    const int n0 = blockIdx.x * BN;     // s-tile offset
    const float* A = g_embs + (size_t)b * SEQL * EDIM;

    __shared__ float As[BKK][BM];
    __shared__ float Bs[BKK][BN];
    __shared__ float red[16][BN];

    const int tid  = threadIdx.x;
    const int trow = tid >> 4;          // 0..15
    const int tcol = tid & 15;          // 0..15
    const int tm   = trow * TM;
    const int tn   = tcol * TN;

    float acc[TM][TN];
#pragma unroll
    for (int i = 0; i < TM; i++)
#pragma unroll
        for (int j = 0; j < TN; j++) acc[i][j] = 0.0f;

    for (int k0 = 0; k0 < KDIM; k0 += BKK) {
        // --- load A tile: 128 rows x 16 cols = 512 float4, 2 per thread ---
#pragma unroll
        for (int q = 0; q < 2; q++) {
            int lid = tid + 256 * q;
            int ar  = lid >> 2;               // 0..127
            int ac  = (lid & 3) << 2;         // 0,4,8,12
            int gl  = m0 + ar;                // global l
            float4 v = make_float4(0.f, 0.f, 0.f, 0.f);
            if (gl < SEQL - 1)
                v = *reinterpret_cast<const float4*>(A + (size_t)gl * EDIM + k0 + ac);
            As[ac + 0][ar] = v.x; As[ac + 1][ar] = v.y;
            As[ac + 2][ar] = v.z; As[ac + 3][ar] = v.w;
        }
        // --- load B tile: Wc[s,k], 128 rows x 16 cols ---
#pragma unroll
        for (int q = 0; q < 2; q++) {
            int lid = tid + 256 * q;
            int br  = lid >> 2;
            int bcc = (lid & 3) << 2;
            float4 v = *reinterpret_cast<const float4*>(
                Wc + (size_t)(n0 + br) * KDIM + k0 + bcc);
            Bs[bcc + 0][br] = v.x; Bs[bcc + 1][br] = v.y;
            Bs[bcc + 2][br] = v.z; Bs[bcc + 3][br] = v.w;
        }
        __syncthreads();

#pragma unroll
        for (int k = 0; k < BKK; k++) {
            float ra[TM], rb[TN];
            // vector reads from smem (8 consecutive floats each)
            *reinterpret_cast<float4*>(&ra[0]) = *reinterpret_cast<const float4*>(&As[k][tm]);
            *reinterpret_cast<float4*>(&ra[4]) = *reinterpret_cast<const float4*>(&As[k][tm + 4]);
            *reinterpret_cast<float4*>(&rb[0]) = *reinterpret_cast<const float4*>(&Bs[k][tn]);
            *reinterpret_cast<float4*>(&rb[4]) = *reinterpret_cast<const float4*>(&Bs[k][tn + 4]);
#pragma unroll
            for (int i = 0; i < TM; i++)
#pragma unroll
                for (int j = 0; j < TN; j++)
                    acc[i][j] = fmaf(ra[i], rb[j], acc[i][j]);
        }
        __syncthreads();
    }

    // --- epilogue: add bias, per-thread max over valid rows ---
    float bcv[TN];
#pragma unroll
    for (int j = 0; j < TN; j++) bcv[j] = __ldg(&bc[n0 + tn + j]);

    float cmax[TN];
#pragma unroll
    for (int j = 0; j < TN; j++) cmax[j] = -CUDART_INF_F;

#pragma unroll
    for (int i = 0; i < TM; i++) {
        int gl = m0 + tm + i;
        if (gl < SEQL - 1) {
#pragma unroll
            for (int j = 0; j < TN; j++)
                cmax[j] = fmaxf(cmax[j], acc[i][j] + bcv[j]);
        }
    }

    // --- tree reduce across the 16 row-groups ---
#pragma unroll
    for (int j = 0; j < TN; j++) red[trow][tn + j] = cmax[j];
    __syncthreads();
#pragma unroll
    for (int st = 8; st > 0; st >>= 1) {
        if (trow < st) {
#pragma unroll
            for (int j = 0; j < TN; j++)
                red[trow][tn + j] = fmaxf(red[trow][tn + j], red[trow + st][tn + j]);
        }
        __syncthreads();
    }
    if (trow == 0) {
#pragma unroll
        for (int j = 0; j < TN; j++)
            atomicMaxFloat(&g_sentpre[(size_t)b * SDIM + n0 + tn + j], red[0][tn + j]);
    }
}

// ---------------------------------------------------------------------------
// Kernel 4: sigmoid + classifier (S->50->2) + log_softmax. One block per b.
// ---------------------------------------------------------------------------
__global__ __launch_bounds__(128) void classifier_kernel(
    const float* __restrict__ W1, const float* __restrict__ b1,
    const float* __restrict__ W2, const float* __restrict__ b2,
    float* __restrict__ out)
{
    const int b = blockIdx.x;
    __shared__ float sent[SDIM];
    __shared__ float h[64];

    for (int i = threadIdx.x; i < SDIM; i += blockDim.x) {
        float v = g_sentpre[(size_t)b * SDIM + i];
        sent[i] = 1.0f / (1.0f + expf(-v));
    }
    __syncthreads();

    const int w    = threadIdx.x >> 5;
    const int lane = threadIdx.x & 31;
    for (int j = w; j < 50; j += 4) {
        float sum = 0.0f;
        const float* wrow = W1 + (size_t)j * SDIM;
        for (int i = lane; i < SDIM; i += 32) sum = fmaf(sent[i], wrow[i], sum);
#pragma unroll
        for (int o = 16; o > 0; o >>= 1) sum += __shfl_down_sync(0xffffffffu, sum, o);
        if (lane == 0) h[j] = sum + b1[j];
    }
    __syncthreads();

    if (threadIdx.x == 0) {
        float l0 = b2[0], l1 = b2[1];
        for (int j = 0; j < 50; j++) {
            l0 = fmaf(h[j], W2[j], l0);
            l1 = fmaf(h[j], W2[50 + j], l1);
        }
        float m   = fmaxf(l0, l1);
        float lse = m + logf(expf(l0 - m) + expf(l1 - m));
        out[b * NCLASS + 0] = l0 - lse;
        out[b * NCLASS + 1] = l1 - lse;
    }
}

// ---------------------------------------------------------------------------
// kernel_launch
// inputs order: inputs(int32), emb_table, Wc, bc, W1, b1, W2, b2
// ---------------------------------------------------------------------------
extern "C" void kernel_launch(void* const* d_in, const int* in_sizes, int n_in,
                              void* d_out, int out_size) {
    const int*   inputs = (const int*)  d_in[0];
    const float* emb    = (const float*)d_in[1];
    const float* Wc     = (const float*)d_in[2];
    const float* bc     = (const float*)d_in[3];
    const float* W1     = (const float*)d_in[4];
    const float* b1     = (const float*)d_in[5];
    const float* W2     = (const float*)d_in[6];
    const float* b2     = (const float*)d_in[7];
    float* out = (float*)d_out;

    gather_kernel<<<BATCH * SEQL, 128>>>(inputs, emb);
    init_kernel<<<(BATCH * SDIM + 255) / 256, 256>>>();

    dim3 grid(SDIM / BN, (SEQL - 1 + BM - 1) / BM, BATCH);
    conv_max_kernel<<<grid, 256>>>(Wc, bc);

    classifier_kernel<<<BATCH, 128>>>(W1, b1, W2, b2, out);
}